// round 13
// baseline (speedup 1.0000x reference)
#include <cuda_runtime.h>

// CRF NLL: B=1024, T=4096, K=16 — bidirectional scan, 8-lane groups.
// Each 8-lane group advances one element; lane r owns states 2r, 2r+1 and
// computes both outputs with packed fma.rn.f32x2. Exchange: STS.64 ->
// syncwarp -> 4x LDS.128 (full vector, conflict-free, 20-float stride).
// 4 elements per warp -> 512 scan warps (1 per SMSP). Gold path scored by a
// dedicated warp per forward block. Combine kernel does fwd=log(w^T M alpha).

#define T_LEN 4096
#define KTAG 16
#define TILE 16
#define START_TAG 14
#define STOP_TAG 15
#define NELEM 1024

typedef unsigned long long ull;

__device__ float gBuf[NELEM][16];
__device__ float wBuf[NELEM][16];
__device__ int   eBufF[NELEM], eBufB[NELEM];
__device__ float goldBuf[NELEM];

__device__ __forceinline__ ull pk2(float lo, float hi) {
    ull d; asm("mov.b64 %0,{%1,%2};" : "=l"(d) : "f"(lo), "f"(hi)); return d;
}
__device__ __forceinline__ void upk2(ull v, float& lo, float& hi) {
    asm("mov.b64 {%0,%1},%2;" : "=f"(lo), "=f"(hi) : "l"(v));
}
__device__ __forceinline__ ull fma2(ull a, ull b, ull c) {
    ull d; asm("fma.rn.f32x2 %0,%1,%2,%3;" : "=l"(d) : "l"(a), "l"(b), "l"(c)); return d;
}
__device__ __forceinline__ ull mul2(ull a, ull b) {
    ull d; asm("mul.rn.f32x2 %0,%1,%2;" : "=l"(d) : "l"(a), "l"(b)); return d;
}
__device__ __forceinline__ ull add2(ull a, ull b) {
    ull d; asm("add.rn.f32x2 %0,%1,%2;" : "=l"(d) : "l"(a), "l"(b)); return d;
}

struct ULL2m { ull a, b; };
union Q16 { float4 f; ULL2m u; };

// one scan step for a lane owning rows j0=2r, j1=2r+1; P = group vector
__device__ __forceinline__ void scan_step(
    float* P, int j0, const ull* Ma, const ull* Mb,
    float ef0, float ef1, bool doRenorm, int& esum,
    float& pn0, float& pn1)
{
    __syncwarp();
    Q16 x0, x1, x2, x3;
    x0.f = *reinterpret_cast<const float4*>(P + 0);
    x1.f = *reinterpret_cast<const float4*>(P + 4);
    x2.f = *reinterpret_cast<const float4*>(P + 8);
    x3.f = *reinterpret_cast<const float4*>(P + 12);

    if (doRenorm) {
        float m0 = fmaxf(fmaxf(x0.f.x, x0.f.y), fmaxf(x0.f.z, x0.f.w));
        float m1 = fmaxf(fmaxf(x1.f.x, x1.f.y), fmaxf(x1.f.z, x1.f.w));
        float m2 = fmaxf(fmaxf(x2.f.x, x2.f.y), fmaxf(x2.f.z, x2.f.w));
        float m3 = fmaxf(fmaxf(x3.f.x, x3.f.y), fmaxf(x3.f.z, x3.f.w));
        float m  = fmaxf(fmaxf(m0, m1), fmaxf(m2, m3));
        int e = (__float_as_int(m) >> 23) & 255;
        float sc = __int_as_float((254 - e) << 23);   // 2^(127-e), exact
        ef0 *= sc; ef1 *= sc;
        esum += e - 127;
    }

    // out0 = dot(row j0, p), out1 = dot(row j1, p)  (packed pairs)
    ull a0 = mul2(Ma[0], x0.u.a);
    ull b0 = mul2(Ma[1], x0.u.b);
    ull a1 = mul2(Mb[0], x0.u.a);
    ull b1 = mul2(Mb[1], x0.u.b);
    a0 = fma2(Ma[2], x1.u.a, a0);
    b0 = fma2(Ma[3], x1.u.b, b0);
    a1 = fma2(Mb[2], x1.u.a, a1);
    b1 = fma2(Mb[3], x1.u.b, b1);
    a0 = fma2(Ma[4], x2.u.a, a0);
    b0 = fma2(Ma[5], x2.u.b, b0);
    a1 = fma2(Mb[4], x2.u.a, a1);
    b1 = fma2(Mb[5], x2.u.b, b1);
    a0 = fma2(Ma[6], x3.u.a, a0);
    b0 = fma2(Ma[7], x3.u.b, b0);
    a1 = fma2(Mb[6], x3.u.a, a1);
    b1 = fma2(Mb[7], x3.u.b, b1);
    a0 = add2(a0, b0);
    a1 = add2(a1, b1);
    float l0, h0, l1, h1;
    upk2(a0, l0, h0);
    upk2(a1, l1, h1);
    pn0 = (l0 + h0) * ef0;
    pn1 = (l1 + h1) * ef1;
    *reinterpret_cast<float2*>(P + j0) = make_float2(pn0, pn1);
}

__global__ __launch_bounds__(160, 1)
void crf_scan_kernel(const float* __restrict__ feats,
                     const int* __restrict__ tags,
                     const float* __restrict__ trans) {
    __shared__ float sExpT[256];
    __shared__ float sLogT[256];
    __shared__ float sP[16][20];    // 16 groups, 20-float stride (bank-clean)

    int tid = threadIdx.x;
    for (int i = tid; i < 256; i += 160) {
        float tv = trans[i];
        sLogT[i] = tv;
        sExpT[i] = __expf(tv);      // exp(-10000) -> 0: correct masking
    }
    __syncthreads();

    bool isFwd = (blockIdx.x < 64);
    int bblk = (isFwd ? blockIdx.x : blockIdx.x - 64) * 16;

    if (tid >= 128) {
        // ------------------ gold warp (fwd blocks only) --------------------
        if (!isFwd) return;
        int lane = tid & 31;
        int g    = lane >> 1;          // element 0..15
        int sub  = lane & 1;           // half of the sequence
        int b    = bblk + g;
        const float* fbase = feats + (size_t)b * T_LEN * KTAG;
        const int*   tptr  = tags  + (size_t)b * T_LEN;

        int t0 = sub * 2048;
        int prev = (sub == 0) ? START_TAG : tptr[t0 - 1];
        float gg = 0.0f;
        for (int t = t0; t < t0 + 2048; t += 4) {
            int4 tg = *reinterpret_cast<const int4*>(tptr + t);
            float f0 = fbase[(t + 0) * KTAG + tg.x];
            float f1 = fbase[(t + 1) * KTAG + tg.y];
            float f2 = fbase[(t + 2) * KTAG + tg.z];
            float f3 = fbase[(t + 3) * KTAG + tg.w];
            gg += f0 + sLogT[tg.x * 16 + prev];
            gg += f1 + sLogT[tg.y * 16 + tg.x];
            gg += f2 + sLogT[tg.z * 16 + tg.y];
            gg += f3 + sLogT[tg.w * 16 + tg.z];
            prev = tg.w;
        }
        if (sub == 1) gg += sLogT[STOP_TAG * 16 + prev];   // terminal
        gg += __shfl_xor_sync(0xffffffffu, gg, 1, 2);
        if (sub == 0) goldBuf[b] = gg;
        return;
    }

    // --------------------------- scan warps --------------------------------
    int lane = tid & 31;
    int r    = lane & 7;              // lane within 8-lane group
    int warp = tid >> 5;              // 0..3
    int gl   = warp * 4 + (lane >> 3);  // group within block, 0..15
    int b    = bblk + gl;
    int j0   = 2 * r;

    const float* fbase = feats + (size_t)b * T_LEN * KTAG;
    float* P = &sP[gl][0];

    // packed row pairs for outputs j0, j0+1 (fwd: rows of M, bwd: rows of M^T)
    ull Ma[8], Mb[8];
    if (isFwd) {
        #pragma unroll
        for (int k = 0; k < 8; k++) {
            Ma[k] = pk2(sExpT[j0 * 16 + 2 * k],       sExpT[j0 * 16 + 2 * k + 1]);
            Mb[k] = pk2(sExpT[(j0 + 1) * 16 + 2 * k], sExpT[(j0 + 1) * 16 + 2 * k + 1]);
        }
    } else {
        #pragma unroll
        for (int k = 0; k < 8; k++) {
            Ma[k] = pk2(sExpT[(2 * k) * 16 + j0],     sExpT[(2 * k + 1) * 16 + j0]);
            Mb[k] = pk2(sExpT[(2 * k) * 16 + j0 + 1], sExpT[(2 * k + 1) * 16 + j0 + 1]);
        }
    }

    if (isFwd) {
        float i0 = (j0 == START_TAG) ? 1.0f : 0.0f;
        *reinterpret_cast<float2*>(P + j0) = make_float2(i0, 0.0f);
    } else {
        // w_4096 = ef_4096 .* u, u_j = expT[STOP][j]
        float2 fl = *reinterpret_cast<const float2*>(fbase + 4095 * KTAG + j0);
        *reinterpret_cast<float2*>(P + j0) = make_float2(
            __expf(fl.x) * sExpT[STOP_TAG * 16 + j0],
            __expf(fl.y) * sExpT[STOP_TAG * 16 + j0 + 1]);
    }

    int   esum = 0;
    float pn0 = 0.0f, pn1 = 0.0f;
    if (!isFwd) { float2 w0 = *reinterpret_cast<float2*>(P + j0); pn0 = w0.x; pn1 = w0.y; }

    float2 fA[TILE], fB[TILE];

    if (isFwd) {
        #pragma unroll
        for (int u = 0; u < TILE; u++)
            fA[u] = *reinterpret_cast<const float2*>(fbase + u * KTAG + j0);

        const int NT = 2048 / TILE;   // 128
        #pragma unroll 1
        for (int tile = 0; tile < NT; tile++) {
            if (tile + 1 < NT) {
                int base = (tile + 1) * TILE;
                #pragma unroll
                for (int u = 0; u < TILE; u++)
                    fB[u] = *reinterpret_cast<const float2*>(fbase + (base + u) * KTAG + j0);
            }
            #pragma unroll
            for (int u = 0; u < TILE; u++) {
                float ef0 = __expf(fA[u].x);
                float ef1 = __expf(fA[u].y);
                scan_step(P, j0, Ma, Mb, ef0, ef1, (u & 3) == 3, esum, pn0, pn1);
            }
            #pragma unroll
            for (int u = 0; u < TILE; u++) fA[u] = fB[u];
        }

        gBuf[b][j0]     = pn0;
        gBuf[b][j0 + 1] = pn1;
        if (r == 0) eBufF[b] = esum;
    } else {
        // backward: idx 4094 down to 2048 (2047 steps: 127 full tiles + 15)
        #pragma unroll
        for (int u = 0; u < TILE; u++)
            fA[u] = *reinterpret_cast<const float2*>(fbase + (4094 - u) * KTAG + j0);

        const int NTB = 128;
        #pragma unroll 1
        for (int tile = 0; tile < NTB - 1; tile++) {
            {
                int hi2 = 4094 - 16 * (tile + 1);
                #pragma unroll
                for (int u = 0; u < TILE; u++)
                    fB[u] = *reinterpret_cast<const float2*>(fbase + (hi2 - u) * KTAG + j0);
            }
            #pragma unroll
            for (int u = 0; u < TILE; u++) {
                float ef0 = __expf(fA[u].x);
                float ef1 = __expf(fA[u].y);
                scan_step(P, j0, Ma, Mb, ef0, ef1, (u & 3) == 3, esum, pn0, pn1);
            }
            #pragma unroll
            for (int u = 0; u < TILE; u++) fA[u] = fB[u];
        }

        #pragma unroll
        for (int u = 0; u < 15; u++) {    // d = 2062 - u
            float ef0 = __expf(fA[u].x);
            float ef1 = __expf(fA[u].y);
            scan_step(P, j0, Ma, Mb, ef0, ef1, (u & 3) == 3, esum, pn0, pn1);
        }

        wBuf[b][j0]     = pn0;
        wBuf[b][j0 + 1] = pn1;
        if (r == 0) eBufB[b] = esum;
    }
}

__global__ void crf_combine_kernel(const float* __restrict__ trans,
                                   float* __restrict__ out) {
    __shared__ float sE[256];
    int t = threadIdx.x;
    sE[t] = __expf(trans[t]);
    __syncthreads();

    int b = blockIdx.x * 256 + t;

    float gv[16], wv[16];
    #pragma unroll
    for (int i = 0; i < 16; i++) gv[i] = gBuf[b][i];
    #pragma unroll
    for (int i = 0; i < 16; i++) wv[i] = wBuf[b][i];

    // fwd_arg = w^T M alpha
    double dot = 0.0;
    #pragma unroll
    for (int jj = 0; jj < 16; jj++) {
        float mg = 0.0f;
        #pragma unroll
        for (int i = 0; i < 16; i++) mg = fmaf(sE[jj * 16 + i], gv[i], mg);
        dot += (double)wv[jj] * (double)mg;
    }

    double fwd = (double)(eBufF[b] + eBufB[b]) * 0.6931471805599453 + log(dot);
    out[b] = (float)(fwd - (double)goldBuf[b]);
}

extern "C" void kernel_launch(void* const* d_in, const int* in_sizes, int n_in,
                              void* d_out, int out_size) {
    const float* feats = (const float*)d_in[0];
    const int*   tags  = (const int*)d_in[1];
    const float* trans = (const float*)d_in[2];
    float* out = (float*)d_out;

    crf_scan_kernel<<<128, 160>>>(feats, tags, trans);
    crf_combine_kernel<<<4, 256>>>(trans, out);
}

// round 14
// speedup vs baseline: 1.4537x; 1.4537x over previous
#include <cuda_runtime.h>

// CRF NLL: B=1024, T=4096, K=16 — bidirectional scan + packed f32x2 matvec.
// Forward half computes alpha_2048 (prob domain, exact pow2 renorm);
// backward half computes w = ef .* (M^T w) down to index 2048;
// last block combines: fwd = log(w^T M alpha) + (esumF+esumB) ln2.
// Renorm scale taken from the state-0 entry (always > 0) — no max tree.
// Gold path scored by a dedicated per-block warp in forward blocks.

#define T_LEN 4096
#define KTAG 16
#define TILE 16
#define START_TAG 14
#define STOP_TAG 15
#define NELEM 1024
#define NBLOCKS 256

typedef unsigned long long ull;

__device__ float gBuf[NELEM][16];    // forward final alpha (scaled)
__device__ float wBuf[NELEM][16];    // backward final w (scaled)
__device__ int   eBufF[NELEM], eBufB[NELEM];
__device__ float goldBuf[NELEM];
__device__ unsigned int doneCtr = 0;

__device__ __forceinline__ ull pk2(float lo, float hi) {
    ull d; asm("mov.b64 %0,{%1,%2};" : "=l"(d) : "f"(lo), "f"(hi)); return d;
}
__device__ __forceinline__ void upk2(ull v, float& lo, float& hi) {
    asm("mov.b64 {%0,%1},%2;" : "=f"(lo), "=f"(hi) : "l"(v));
}
__device__ __forceinline__ ull fma2(ull a, ull b, ull c) {
    ull d; asm("fma.rn.f32x2 %0,%1,%2,%3;" : "=l"(d) : "l"(a), "l"(b), "l"(c)); return d;
}
__device__ __forceinline__ ull mul2(ull a, ull b) {
    ull d; asm("mul.rn.f32x2 %0,%1,%2;" : "=l"(d) : "l"(a), "l"(b)); return d;
}
__device__ __forceinline__ ull add2(ull a, ull b) {
    ull d; asm("add.rn.f32x2 %0,%1,%2;" : "=l"(d) : "l"(a), "l"(b)); return d;
}

struct ULL2m { ull a, b; };
union Q16 { float4 f; ULL2m u; };

__global__ __launch_bounds__(160, 1)
void crf_scan_kernel(const float* __restrict__ feats,
                     const int* __restrict__ tags,
                     const float* __restrict__ trans,
                     float* __restrict__ out) {
    __shared__ float sExpT[256];
    __shared__ float sLogT[256];
    __shared__ float sP[8][16];
    __shared__ int   sLast;

    int tid = threadIdx.x;
    for (int i = tid; i < 256; i += 160) {
        float tv = trans[i];
        sLogT[i] = tv;
        sExpT[i] = __expf(tv);     // exp(-10000) -> 0: correct masking
    }
    __syncthreads();

    bool isFwd = (blockIdx.x < 128);
    int bblk = (isFwd ? blockIdx.x : blockIdx.x - 128) * 8;

    if (tid >= 128) {
        // ---------------- gold warp (fwd blocks only) ----------------------
        if (isFwd) {
            int lane = tid & 31;
            int g    = lane >> 2;          // element 0..7
            int sub  = lane & 3;           // quarter of the sequence
            int b    = bblk + g;
            const float* fbase = feats + (size_t)b * T_LEN * KTAG;
            const int*   tptr  = tags  + (size_t)b * T_LEN;

            int t0 = sub * 1024;
            int prev = (sub == 0) ? START_TAG : tptr[t0 - 1];
            float gg = 0.0f;
            for (int t = t0; t < t0 + 1024; t += 4) {
                int4 tg = *reinterpret_cast<const int4*>(tptr + t);
                float f0 = fbase[(t + 0) * KTAG + tg.x];
                float f1 = fbase[(t + 1) * KTAG + tg.y];
                float f2 = fbase[(t + 2) * KTAG + tg.z];
                float f3 = fbase[(t + 3) * KTAG + tg.w];
                gg += f0 + sLogT[tg.x * 16 + prev];
                gg += f1 + sLogT[tg.y * 16 + tg.x];
                gg += f2 + sLogT[tg.z * 16 + tg.y];
                gg += f3 + sLogT[tg.w * 16 + tg.z];
                prev = tg.w;
            }
            if (sub == 3) gg += sLogT[STOP_TAG * 16 + prev];   // terminal
            gg += __shfl_xor_sync(0xffffffffu, gg, 1, 4);
            gg += __shfl_xor_sync(0xffffffffu, gg, 2, 4);
            if (sub == 0) goldBuf[b] = gg;
        }
    } else {
        // ------------------------- scan warps ------------------------------
        int lane = tid & 31;
        int grp  = lane >> 4;
        int j    = lane & 15;
        int warp = tid >> 5;
        int g    = warp * 2 + grp;
        int b    = bblk + g;

        const float* fbase = feats + (size_t)b * T_LEN * KTAG;
        float* P = &sP[g][0];

        // packed row pairs: fwd rows of M, bwd rows of M^T
        ull Mp[8];
        if (isFwd) {
            #pragma unroll
            for (int k = 0; k < 8; k++)
                Mp[k] = pk2(sExpT[j * 16 + 2 * k], sExpT[j * 16 + 2 * k + 1]);
        } else {
            #pragma unroll
            for (int k = 0; k < 8; k++)
                Mp[k] = pk2(sExpT[(2 * k) * 16 + j], sExpT[(2 * k + 1) * 16 + j]);
        }

        if (isFwd) {
            P[j] = (j == START_TAG) ? 1.0f : 0.0f;
        } else {
            // w_4096 = ef_4096 .* u, u_j = expT[STOP][j]
            P[j] = __expf(fbase[4095 * KTAG + j]) * sExpT[STOP_TAG * 16 + j];
        }
        __syncwarp();

        int   esum = 0;
        float pnew = isFwd ? 0.0f : P[j];

        float fA[TILE], fB[TILE];

        if (isFwd) {
            #pragma unroll
            for (int u = 0; u < TILE; u++) fA[u] = fbase[u * KTAG + j];

            const int NT = 2048 / TILE;   // 128
            #pragma unroll 1
            for (int tile = 0; tile < NT; tile++) {
                if (tile + 1 < NT) {
                    int base = (tile + 1) * TILE;
                    #pragma unroll
                    for (int u = 0; u < TILE; u++) fB[u] = fbase[(base + u) * KTAG + j];
                }
                #pragma unroll
                for (int u = 0; u < TILE; u++) {
                    float ef = __expf(fA[u]);
                    __syncwarp();
                    Q16 x0, x1, x2, x3;
                    x0.f = *reinterpret_cast<const float4*>(P + 0);
                    x1.f = *reinterpret_cast<const float4*>(P + 4);
                    x2.f = *reinterpret_cast<const float4*>(P + 8);
                    x3.f = *reinterpret_cast<const float4*>(P + 12);

                    if ((u & 3) == 3) {
                        // renorm by exponent of state-0 entry (always > 0)
                        int e = (__float_as_int(x0.f.x) >> 23) & 255;
                        ef *= __int_as_float((254 - e) << 23);   // 2^(127-e), exact
                        esum += e - 127;
                    }

                    ull a0 = mul2(Mp[0], x0.u.a);
                    ull a1 = mul2(Mp[1], x0.u.b);
                    ull a2 = mul2(Mp[2], x1.u.a);
                    ull a3 = mul2(Mp[3], x1.u.b);
                    a0 = fma2(Mp[4], x2.u.a, a0);
                    a1 = fma2(Mp[5], x2.u.b, a1);
                    a2 = fma2(Mp[6], x3.u.a, a2);
                    a3 = fma2(Mp[7], x3.u.b, a3);
                    a0 = add2(a0, a1);
                    a2 = add2(a2, a3);
                    a0 = add2(a0, a2);
                    float lo, hi; upk2(a0, lo, hi);
                    pnew = (lo + hi) * ef;
                    P[j] = pnew;
                }
                #pragma unroll
                for (int u = 0; u < TILE; u++) fA[u] = fB[u];
            }

            gBuf[b][j] = pnew;
            if (j == 0) eBufF[b] = esum;
        } else {
            // backward: idx 4094 down to 2048 (127 full tiles + 15 steps)
            #pragma unroll
            for (int u = 0; u < TILE; u++) fA[u] = fbase[(4094 - u) * KTAG + j];

            const int NTB = 128;
            #pragma unroll 1
            for (int tile = 0; tile < NTB - 1; tile++) {
                {
                    int hi2 = 4094 - 16 * (tile + 1);
                    #pragma unroll
                    for (int u = 0; u < TILE; u++) fB[u] = fbase[(hi2 - u) * KTAG + j];
                }
                #pragma unroll
                for (int u = 0; u < TILE; u++) {
                    float ef = __expf(fA[u]);
                    __syncwarp();
                    Q16 x0, x1, x2, x3;
                    x0.f = *reinterpret_cast<const float4*>(P + 0);
                    x1.f = *reinterpret_cast<const float4*>(P + 4);
                    x2.f = *reinterpret_cast<const float4*>(P + 8);
                    x3.f = *reinterpret_cast<const float4*>(P + 12);

                    if ((u & 3) == 3) {
                        int e = (__float_as_int(x0.f.x) >> 23) & 255;
                        ef *= __int_as_float((254 - e) << 23);
                        esum += e - 127;
                    }

                    ull a0 = mul2(Mp[0], x0.u.a);
                    ull a1 = mul2(Mp[1], x0.u.b);
                    ull a2 = mul2(Mp[2], x1.u.a);
                    ull a3 = mul2(Mp[3], x1.u.b);
                    a0 = fma2(Mp[4], x2.u.a, a0);
                    a1 = fma2(Mp[5], x2.u.b, a1);
                    a2 = fma2(Mp[6], x3.u.a, a2);
                    a3 = fma2(Mp[7], x3.u.b, a3);
                    a0 = add2(a0, a1);
                    a2 = add2(a2, a3);
                    a0 = add2(a0, a2);
                    float lo, hi; upk2(a0, lo, hi);
                    pnew = (lo + hi) * ef;
                    P[j] = pnew;
                }
                #pragma unroll
                for (int u = 0; u < TILE; u++) fA[u] = fB[u];
            }

            #pragma unroll
            for (int u = 0; u < 15; u++) {     // d = 2062 - u
                float ef = __expf(fA[u]);
                __syncwarp();
                Q16 x0, x1, x2, x3;
                x0.f = *reinterpret_cast<const float4*>(P + 0);
                x1.f = *reinterpret_cast<const float4*>(P + 4);
                x2.f = *reinterpret_cast<const float4*>(P + 8);
                x3.f = *reinterpret_cast<const float4*>(P + 12);

                if ((u & 3) == 3) {
                    int e = (__float_as_int(x0.f.x) >> 23) & 255;
                    ef *= __int_as_float((254 - e) << 23);
                    esum += e - 127;
                }

                ull a0 = mul2(Mp[0], x0.u.a);
                ull a1 = mul2(Mp[1], x0.u.b);
                ull a2 = mul2(Mp[2], x1.u.a);
                ull a3 = mul2(Mp[3], x1.u.b);
                a0 = fma2(Mp[4], x2.u.a, a0);
                a1 = fma2(Mp[5], x2.u.b, a1);
                a2 = fma2(Mp[6], x3.u.a, a2);
                a3 = fma2(Mp[7], x3.u.b, a3);
                a0 = add2(a0, a1);
                a2 = add2(a2, a3);
                a0 = add2(a0, a2);
                float lo, hi; upk2(a0, lo, hi);
                pnew = (lo + hi) * ef;
                P[j] = pnew;
            }

            wBuf[b][j] = pnew;
            if (j == 0) eBufB[b] = esum;
        }
    }

    // -------------------- fused combine: last block only -------------------
    __syncthreads();
    if (tid == 0) {
        __threadfence();                       // release our gBuf/wBuf writes
        unsigned done = atomicAdd(&doneCtr, 1);
        sLast = (done == NBLOCKS - 1) ? 1 : 0;
    }
    __syncthreads();
    if (!sLast) return;
    __threadfence();                           // acquire all blocks' writes

    for (int b = tid; b < NELEM; b += 160) {
        float gv[16], wv[16];
        #pragma unroll
        for (int i = 0; i < 16; i++) gv[i] = gBuf[b][i];
        #pragma unroll
        for (int i = 0; i < 16; i++) wv[i] = wBuf[b][i];

        double dot = 0.0;                      // fwd_arg = w^T M alpha
        #pragma unroll
        for (int jj = 0; jj < 16; jj++) {
            float mg = 0.0f;
            #pragma unroll
            for (int i = 0; i < 16; i++) mg = fmaf(sExpT[jj * 16 + i], gv[i], mg);
            dot += (double)wv[jj] * (double)mg;
        }

        double fwd = (double)(eBufF[b] + eBufB[b]) * 0.6931471805599453 + log(dot);
        out[b] = (float)(fwd - (double)goldBuf[b]);
    }

    __syncthreads();
    if (tid == 0) doneCtr = 0;                 // reset for next graph replay
}

extern "C" void kernel_launch(void* const* d_in, const int* in_sizes, int n_in,
                              void* d_out, int out_size) {
    const float* feats = (const float*)d_in[0];
    const int*   tags  = (const int*)d_in[1];
    const float* trans = (const float*)d_in[2];
    float* out = (float*)d_out;

    crf_scan_kernel<<<NBLOCKS, 160>>>(feats, tags, trans, out);
}

// round 16
// speedup vs baseline: 2.2717x; 1.5627x over previous
#include <cuda_runtime.h>

// CRF NLL: B=1024, T=4096, K=16 — bidirectional scan + packed f32x2 matvec.
// Forward half computes alpha_2048 (prob domain, exact pow2 renorm);
// backward half computes w = ef .* (M^T w) down to index 2048;
// combine kernel evaluates fwd = log(w^T M alpha) + (esumF+esumB) ln2.
// Renorm scale = exponent of the state-0 entry (always > 0; validated) —
// no max tree. Gold path scored by a dedicated per-block warp.

#define T_LEN 4096
#define KTAG 16
#define TILE 16
#define START_TAG 14
#define STOP_TAG 15
#define NELEM 1024

typedef unsigned long long ull;

__device__ float gBuf[NELEM][16];    // forward final alpha (scaled)
__device__ float wBuf[NELEM][16];    // backward final w (scaled)
__device__ int   eBufF[NELEM], eBufB[NELEM];
__device__ float goldBuf[NELEM];

__device__ __forceinline__ ull pk2(float lo, float hi) {
    ull d; asm("mov.b64 %0,{%1,%2};" : "=l"(d) : "f"(lo), "f"(hi)); return d;
}
__device__ __forceinline__ void upk2(ull v, float& lo, float& hi) {
    asm("mov.b64 {%0,%1},%2;" : "=f"(lo), "=f"(hi) : "l"(v));
}
__device__ __forceinline__ ull fma2(ull a, ull b, ull c) {
    ull d; asm("fma.rn.f32x2 %0,%1,%2,%3;" : "=l"(d) : "l"(a), "l"(b), "l"(c)); return d;
}
__device__ __forceinline__ ull mul2(ull a, ull b) {
    ull d; asm("mul.rn.f32x2 %0,%1,%2;" : "=l"(d) : "l"(a), "l"(b)); return d;
}
__device__ __forceinline__ ull add2(ull a, ull b) {
    ull d; asm("add.rn.f32x2 %0,%1,%2;" : "=l"(d) : "l"(a), "l"(b)); return d;
}

struct ULL2m { ull a, b; };
union Q16 { float4 f; ULL2m u; };

__global__ __launch_bounds__(160, 1)
void crf_scan_kernel(const float* __restrict__ feats,
                     const int* __restrict__ tags,
                     const float* __restrict__ trans) {
    __shared__ float sExpT[256];
    __shared__ float sLogT[256];
    __shared__ float sP[8][16];

    int tid = threadIdx.x;
    for (int i = tid; i < 256; i += 160) {
        float tv = trans[i];
        sLogT[i] = tv;
        sExpT[i] = __expf(tv);     // exp(-10000) -> 0: correct masking
    }
    __syncthreads();

    bool isFwd = (blockIdx.x < 128);
    int bblk = (isFwd ? blockIdx.x : blockIdx.x - 128) * 8;

    if (tid >= 128) {
        // ---------------- gold warp (fwd blocks only) ----------------------
        if (!isFwd) return;
        int lane = tid & 31;
        int g    = lane >> 2;          // element 0..7
        int sub  = lane & 3;           // quarter of the sequence
        int b    = bblk + g;
        const float* fbase = feats + (size_t)b * T_LEN * KTAG;
        const int*   tptr  = tags  + (size_t)b * T_LEN;

        int t0 = sub * 1024;
        int prev = (sub == 0) ? START_TAG : tptr[t0 - 1];
        float gg = 0.0f;
        for (int t = t0; t < t0 + 1024; t += 4) {
            int4 tg = *reinterpret_cast<const int4*>(tptr + t);
            float f0 = fbase[(t + 0) * KTAG + tg.x];
            float f1 = fbase[(t + 1) * KTAG + tg.y];
            float f2 = fbase[(t + 2) * KTAG + tg.z];
            float f3 = fbase[(t + 3) * KTAG + tg.w];
            gg += f0 + sLogT[tg.x * 16 + prev];
            gg += f1 + sLogT[tg.y * 16 + tg.x];
            gg += f2 + sLogT[tg.z * 16 + tg.y];
            gg += f3 + sLogT[tg.w * 16 + tg.z];
            prev = tg.w;
        }
        if (sub == 3) gg += sLogT[STOP_TAG * 16 + prev];   // terminal
        gg += __shfl_xor_sync(0xffffffffu, gg, 1, 4);
        gg += __shfl_xor_sync(0xffffffffu, gg, 2, 4);
        if (sub == 0) goldBuf[b] = gg;
        return;
    }

    // ------------------------- scan warps ---------------------------------
    int lane = tid & 31;
    int grp  = lane >> 4;
    int j    = lane & 15;
    int warp = tid >> 5;
    int g    = warp * 2 + grp;
    int b    = bblk + g;

    const float* fbase = feats + (size_t)b * T_LEN * KTAG;
    float* P = &sP[g][0];

    // packed row pairs: fwd uses rows of M, bwd uses rows of M^T
    ull Mp[8];
    if (isFwd) {
        #pragma unroll
        for (int k = 0; k < 8; k++)
            Mp[k] = pk2(sExpT[j * 16 + 2 * k], sExpT[j * 16 + 2 * k + 1]);
    } else {
        #pragma unroll
        for (int k = 0; k < 8; k++)
            Mp[k] = pk2(sExpT[(2 * k) * 16 + j], sExpT[(2 * k + 1) * 16 + j]);
    }

    if (isFwd) {
        P[j] = (j == START_TAG) ? 1.0f : 0.0f;
    } else {
        // w_4096 = ef_4096 .* u,  u_j = expT[STOP][j]
        P[j] = __expf(fbase[4095 * KTAG + j]) * sExpT[STOP_TAG * 16 + j];
    }
    __syncwarp();

    int   esum = 0;
    float pnew = isFwd ? 0.0f : P[j];

    float fA[TILE], fB[TILE];

    if (isFwd) {
        #pragma unroll
        for (int u = 0; u < TILE; u++) fA[u] = fbase[u * KTAG + j];

        const int NT = 2048 / TILE;   // 128
        #pragma unroll 1
        for (int tile = 0; tile < NT; tile++) {
            if (tile + 1 < NT) {
                int base = (tile + 1) * TILE;
                #pragma unroll
                for (int u = 0; u < TILE; u++) fB[u] = fbase[(base + u) * KTAG + j];
            }
            #pragma unroll
            for (int u = 0; u < TILE; u++) {
                float ef = __expf(fA[u]);
                __syncwarp();
                Q16 x0, x1, x2, x3;
                x0.f = *reinterpret_cast<const float4*>(P + 0);
                x1.f = *reinterpret_cast<const float4*>(P + 4);
                x2.f = *reinterpret_cast<const float4*>(P + 8);
                x3.f = *reinterpret_cast<const float4*>(P + 12);

                if ((u & 3) == 3) {
                    // renorm by exponent of state-0 entry (always > 0)
                    int e = (__float_as_int(x0.f.x) >> 23) & 255;
                    ef *= __int_as_float((254 - e) << 23);   // 2^(127-e), exact
                    esum += e - 127;
                }

                ull a0 = mul2(Mp[0], x0.u.a);
                ull a1 = mul2(Mp[1], x0.u.b);
                ull a2 = mul2(Mp[2], x1.u.a);
                ull a3 = mul2(Mp[3], x1.u.b);
                a0 = fma2(Mp[4], x2.u.a, a0);
                a1 = fma2(Mp[5], x2.u.b, a1);
                a2 = fma2(Mp[6], x3.u.a, a2);
                a3 = fma2(Mp[7], x3.u.b, a3);
                a0 = add2(a0, a1);
                a2 = add2(a2, a3);
                a0 = add2(a0, a2);
                float lo, hi; upk2(a0, lo, hi);
                pnew = (lo + hi) * ef;
                P[j] = pnew;
            }
            #pragma unroll
            for (int u = 0; u < TILE; u++) fA[u] = fB[u];
        }

        gBuf[b][j] = pnew;
        if (j == 0) eBufF[b] = esum;
    } else {
        // backward: idx 4094 down to 2048 (2047 steps: 127 full tiles + 15)
        #pragma unroll
        for (int u = 0; u < TILE; u++) fA[u] = fbase[(4094 - u) * KTAG + j];

        const int NTB = 128;
        #pragma unroll 1
        for (int tile = 0; tile < NTB - 1; tile++) {
            {
                int hi2 = 4094 - 16 * (tile + 1);
                #pragma unroll
                for (int u = 0; u < TILE; u++) fB[u] = fbase[(hi2 - u) * KTAG + j];
            }
            #pragma unroll
            for (int u = 0; u < TILE; u++) {
                float ef = __expf(fA[u]);
                __syncwarp();
                Q16 x0, x1, x2, x3;
                x0.f = *reinterpret_cast<const float4*>(P + 0);
                x1.f = *reinterpret_cast<const float4*>(P + 4);
                x2.f = *reinterpret_cast<const float4*>(P + 8);
                x3.f = *reinterpret_cast<const float4*>(P + 12);

                if ((u & 3) == 3) {
                    int e = (__float_as_int(x0.f.x) >> 23) & 255;
                    ef *= __int_as_float((254 - e) << 23);
                    esum += e - 127;
                }

                ull a0 = mul2(Mp[0], x0.u.a);
                ull a1 = mul2(Mp[1], x0.u.b);
                ull a2 = mul2(Mp[2], x1.u.a);
                ull a3 = mul2(Mp[3], x1.u.b);
                a0 = fma2(Mp[4], x2.u.a, a0);
                a1 = fma2(Mp[5], x2.u.b, a1);
                a2 = fma2(Mp[6], x3.u.a, a2);
                a3 = fma2(Mp[7], x3.u.b, a3);
                a0 = add2(a0, a1);
                a2 = add2(a2, a3);
                a0 = add2(a0, a2);
                float lo, hi; upk2(a0, lo, hi);
                pnew = (lo + hi) * ef;
                P[j] = pnew;
            }
            #pragma unroll
            for (int u = 0; u < TILE; u++) fA[u] = fB[u];
        }

        #pragma unroll
        for (int u = 0; u < 15; u++) {     // d = 2062 - u
            float ef = __expf(fA[u]);
            __syncwarp();
            Q16 x0, x1, x2, x3;
            x0.f = *reinterpret_cast<const float4*>(P + 0);
            x1.f = *reinterpret_cast<const float4*>(P + 4);
            x2.f = *reinterpret_cast<const float4*>(P + 8);
            x3.f = *reinterpret_cast<const float4*>(P + 12);

            if ((u & 3) == 3) {
                int e = (__float_as_int(x0.f.x) >> 23) & 255;
                ef *= __int_as_float((254 - e) << 23);
                esum += e - 127;
            }

            ull a0 = mul2(Mp[0], x0.u.a);
            ull a1 = mul2(Mp[1], x0.u.b);
            ull a2 = mul2(Mp[2], x1.u.a);
            ull a3 = mul2(Mp[3], x1.u.b);
            a0 = fma2(Mp[4], x2.u.a, a0);
            a1 = fma2(Mp[5], x2.u.b, a1);
            a2 = fma2(Mp[6], x3.u.a, a2);
            a3 = fma2(Mp[7], x3.u.b, a3);
            a0 = add2(a0, a1);
            a2 = add2(a2, a3);
            a0 = add2(a0, a2);
            float lo, hi; upk2(a0, lo, hi);
            pnew = (lo + hi) * ef;
            P[j] = pnew;
        }

        wBuf[b][j] = pnew;
        if (j == 0) eBufB[b] = esum;
    }
}

__global__ void crf_combine_kernel(const float* __restrict__ trans,
                                   float* __restrict__ out) {
    __shared__ float sE[256];
    int t = threadIdx.x;
    sE[t] = __expf(trans[t]);
    __syncthreads();

    int b = blockIdx.x * 256 + t;

    float gv[16], wv[16];
    #pragma unroll
    for (int i = 0; i < 16; i++) gv[i] = gBuf[b][i];
    #pragma unroll
    for (int i = 0; i < 16; i++) wv[i] = wBuf[b][i];

    // fwd_arg = w^T M alpha
    double dot = 0.0;
    #pragma unroll
    for (int jj = 0; jj < 16; jj++) {
        float mg = 0.0f;
        #pragma unroll
        for (int i = 0; i < 16; i++) mg = fmaf(sE[jj * 16 + i], gv[i], mg);
        dot += (double)wv[jj] * (double)mg;
    }

    double fwd = (double)(eBufF[b] + eBufB[b]) * 0.6931471805599453 + log(dot);
    out[b] = (float)(fwd - (double)goldBuf[b]);
}

extern "C" void kernel_launch(void* const* d_in, const int* in_sizes, int n_in,
                              void* d_out, int out_size) {
    const float* feats = (const float*)d_in[0];
    const int*   tags  = (const int*)d_in[1];
    const float* trans = (const float*)d_in[2];
    float* out = (float*)d_out;

    crf_scan_kernel<<<256, 160>>>(feats, tags, trans);
    crf_combine_kernel<<<4, 256>>>(trans, out);
}

// round 17
// speedup vs baseline: 2.3172x; 1.0200x over previous
#include <cuda_runtime.h>

// CRF NLL: B=1024, T=4096, K=16 — bidirectional scan + packed f32x2 matvec.
// Topology: 128 blocks (one per SM) x 288 threads = 8 scan warps (fwd+bwd
// chains of the block's 8 elements) + 1 gold warp. Uniform 2.25 warps/SMSP.
// Step body identical to the validated R15 kernel (renorm-lite: scale from
// state-0 exponent, exact pow2, integer esum).

#define T_LEN 4096
#define KTAG 16
#define TILE 16
#define START_TAG 14
#define STOP_TAG 15
#define NELEM 1024

typedef unsigned long long ull;

__device__ float gBuf[NELEM][16];    // forward final alpha (scaled)
__device__ float wBuf[NELEM][16];    // backward final w (scaled)
__device__ int   eBufF[NELEM], eBufB[NELEM];
__device__ float goldBuf[NELEM];

__device__ __forceinline__ ull pk2(float lo, float hi) {
    ull d; asm("mov.b64 %0,{%1,%2};" : "=l"(d) : "f"(lo), "f"(hi)); return d;
}
__device__ __forceinline__ void upk2(ull v, float& lo, float& hi) {
    asm("mov.b64 {%0,%1},%2;" : "=f"(lo), "=f"(hi) : "l"(v));
}
__device__ __forceinline__ ull fma2(ull a, ull b, ull c) {
    ull d; asm("fma.rn.f32x2 %0,%1,%2,%3;" : "=l"(d) : "l"(a), "l"(b), "l"(c)); return d;
}
__device__ __forceinline__ ull mul2(ull a, ull b) {
    ull d; asm("mul.rn.f32x2 %0,%1,%2;" : "=l"(d) : "l"(a), "l"(b)); return d;
}
__device__ __forceinline__ ull add2(ull a, ull b) {
    ull d; asm("add.rn.f32x2 %0,%1,%2;" : "=l"(d) : "l"(a), "l"(b)); return d;
}

struct ULL2m { ull a, b; };
union Q16 { float4 f; ULL2m u; };

__global__ __launch_bounds__(288, 1)
void crf_scan_kernel(const float* __restrict__ feats,
                     const int* __restrict__ tags,
                     const float* __restrict__ trans) {
    __shared__ float sExpT[256];
    __shared__ float sLogT[256];
    __shared__ float sP[16][16];   // 8 fwd + 8 bwd vectors

    int tid = threadIdx.x;
    for (int i = tid; i < 256; i += 288) {
        float tv = trans[i];
        sLogT[i] = tv;
        sExpT[i] = __expf(tv);     // exp(-10000) -> 0: correct masking
    }
    __syncthreads();

    int bblk = blockIdx.x * 8;     // 128 blocks x 8 elements

    if (tid >= 256) {
        // ---------------- gold warp: 8 elements x 4 subsegments ------------
        int lane = tid - 256;
        int g    = lane >> 2;
        int sub  = lane & 3;
        int b    = bblk + g;
        const float* fbase = feats + (size_t)b * T_LEN * KTAG;
        const int*   tptr  = tags  + (size_t)b * T_LEN;

        int t0 = sub * 1024;
        int prev = (sub == 0) ? START_TAG : tptr[t0 - 1];
        float gg = 0.0f;
        for (int t = t0; t < t0 + 1024; t += 4) {
            int4 tg = *reinterpret_cast<const int4*>(tptr + t);
            float f0 = fbase[(t + 0) * KTAG + tg.x];
            float f1 = fbase[(t + 1) * KTAG + tg.y];
            float f2 = fbase[(t + 2) * KTAG + tg.z];
            float f3 = fbase[(t + 3) * KTAG + tg.w];
            gg += f0 + sLogT[tg.x * 16 + prev];
            gg += f1 + sLogT[tg.y * 16 + tg.x];
            gg += f2 + sLogT[tg.z * 16 + tg.y];
            gg += f3 + sLogT[tg.w * 16 + tg.z];
            prev = tg.w;
        }
        if (sub == 3) gg += sLogT[STOP_TAG * 16 + prev];   // terminal
        gg += __shfl_xor_sync(0xffffffffu, gg, 1, 4);
        gg += __shfl_xor_sync(0xffffffffu, gg, 2, 4);
        if (sub == 0) goldBuf[b] = gg;
        return;
    }

    // ------------------------- scan warps ---------------------------------
    int lane = tid & 31;
    int grp  = lane >> 4;
    int j    = lane & 15;
    int warp = tid >> 5;              // 0..7
    bool isFwd = (warp < 4);
    int g    = (warp & 3) * 2 + grp;  // element 0..7 within block
    int b    = bblk + g;

    const float* fbase = feats + (size_t)b * T_LEN * KTAG;
    float* P = &sP[(isFwd ? 0 : 8) + g][0];

    // packed row pairs: fwd uses rows of M, bwd uses rows of M^T
    ull Mp[8];
    if (isFwd) {
        #pragma unroll
        for (int k = 0; k < 8; k++)
            Mp[k] = pk2(sExpT[j * 16 + 2 * k], sExpT[j * 16 + 2 * k + 1]);
    } else {
        #pragma unroll
        for (int k = 0; k < 8; k++)
            Mp[k] = pk2(sExpT[(2 * k) * 16 + j], sExpT[(2 * k + 1) * 16 + j]);
    }

    if (isFwd) {
        P[j] = (j == START_TAG) ? 1.0f : 0.0f;
    } else {
        // w_4096 = ef_4096 .* u,  u_j = expT[STOP][j]
        P[j] = __expf(fbase[4095 * KTAG + j]) * sExpT[STOP_TAG * 16 + j];
    }
    __syncwarp();

    int   esum = 0;
    float pnew = isFwd ? 0.0f : P[j];

    float fA[TILE], fB[TILE];

    if (isFwd) {
        #pragma unroll
        for (int u = 0; u < TILE; u++) fA[u] = fbase[u * KTAG + j];

        const int NT = 2048 / TILE;   // 128
        #pragma unroll 1
        for (int tile = 0; tile < NT; tile++) {
            if (tile + 1 < NT) {
                int base = (tile + 1) * TILE;
                #pragma unroll
                for (int u = 0; u < TILE; u++) fB[u] = fbase[(base + u) * KTAG + j];
            }
            #pragma unroll
            for (int u = 0; u < TILE; u++) {
                float ef = __expf(fA[u]);
                __syncwarp();
                Q16 x0, x1, x2, x3;
                x0.f = *reinterpret_cast<const float4*>(P + 0);
                x1.f = *reinterpret_cast<const float4*>(P + 4);
                x2.f = *reinterpret_cast<const float4*>(P + 8);
                x3.f = *reinterpret_cast<const float4*>(P + 12);

                if ((u & 3) == 3) {
                    // renorm by exponent of state-0 entry (always > 0)
                    int e = (__float_as_int(x0.f.x) >> 23) & 255;
                    ef *= __int_as_float((254 - e) << 23);   // 2^(127-e), exact
                    esum += e - 127;
                }

                ull a0 = mul2(Mp[0], x0.u.a);
                ull a1 = mul2(Mp[1], x0.u.b);
                ull a2 = mul2(Mp[2], x1.u.a);
                ull a3 = mul2(Mp[3], x1.u.b);
                a0 = fma2(Mp[4], x2.u.a, a0);
                a1 = fma2(Mp[5], x2.u.b, a1);
                a2 = fma2(Mp[6], x3.u.a, a2);
                a3 = fma2(Mp[7], x3.u.b, a3);
                a0 = add2(a0, a1);
                a2 = add2(a2, a3);
                a0 = add2(a0, a2);
                float lo, hi; upk2(a0, lo, hi);
                pnew = (lo + hi) * ef;
                P[j] = pnew;
            }
            #pragma unroll
            for (int u = 0; u < TILE; u++) fA[u] = fB[u];
        }

        gBuf[b][j] = pnew;
        if (j == 0) eBufF[b] = esum;
    } else {
        // backward: idx 4094 down to 2048 (2047 steps: 127 full tiles + 15)
        #pragma unroll
        for (int u = 0; u < TILE; u++) fA[u] = fbase[(4094 - u) * KTAG + j];

        const int NTB = 128;
        #pragma unroll 1
        for (int tile = 0; tile < NTB - 1; tile++) {
            {
                int hi2 = 4094 - 16 * (tile + 1);
                #pragma unroll
                for (int u = 0; u < TILE; u++) fB[u] = fbase[(hi2 - u) * KTAG + j];
            }
            #pragma unroll
            for (int u = 0; u < TILE; u++) {
                float ef = __expf(fA[u]);
                __syncwarp();
                Q16 x0, x1, x2, x3;
                x0.f = *reinterpret_cast<const float4*>(P + 0);
                x1.f = *reinterpret_cast<const float4*>(P + 4);
                x2.f = *reinterpret_cast<const float4*>(P + 8);
                x3.f = *reinterpret_cast<const float4*>(P + 12);

                if ((u & 3) == 3) {
                    int e = (__float_as_int(x0.f.x) >> 23) & 255;
                    ef *= __int_as_float((254 - e) << 23);
                    esum += e - 127;
                }

                ull a0 = mul2(Mp[0], x0.u.a);
                ull a1 = mul2(Mp[1], x0.u.b);
                ull a2 = mul2(Mp[2], x1.u.a);
                ull a3 = mul2(Mp[3], x1.u.b);
                a0 = fma2(Mp[4], x2.u.a, a0);
                a1 = fma2(Mp[5], x2.u.b, a1);
                a2 = fma2(Mp[6], x3.u.a, a2);
                a3 = fma2(Mp[7], x3.u.b, a3);
                a0 = add2(a0, a1);
                a2 = add2(a2, a3);
                a0 = add2(a0, a2);
                float lo, hi; upk2(a0, lo, hi);
                pnew = (lo + hi) * ef;
                P[j] = pnew;
            }
            #pragma unroll
            for (int u = 0; u < TILE; u++) fA[u] = fB[u];
        }

        #pragma unroll
        for (int u = 0; u < 15; u++) {     // d = 2062 - u
            float ef = __expf(fA[u]);
            __syncwarp();
            Q16 x0, x1, x2, x3;
            x0.f = *reinterpret_cast<const float4*>(P + 0);
            x1.f = *reinterpret_cast<const float4*>(P + 4);
            x2.f = *reinterpret_cast<const float4*>(P + 8);
            x3.f = *reinterpret_cast<const float4*>(P + 12);

            if ((u & 3) == 3) {
                int e = (__float_as_int(x0.f.x) >> 23) & 255;
                ef *= __int_as_float((254 - e) << 23);
                esum += e - 127;
            }

            ull a0 = mul2(Mp[0], x0.u.a);
            ull a1 = mul2(Mp[1], x0.u.b);
            ull a2 = mul2(Mp[2], x1.u.a);
            ull a3 = mul2(Mp[3], x1.u.b);
            a0 = fma2(Mp[4], x2.u.a, a0);
            a1 = fma2(Mp[5], x2.u.b, a1);
            a2 = fma2(Mp[6], x3.u.a, a2);
            a3 = fma2(Mp[7], x3.u.b, a3);
            a0 = add2(a0, a1);
            a2 = add2(a2, a3);
            a0 = add2(a0, a2);
            float lo, hi; upk2(a0, lo, hi);
            pnew = (lo + hi) * ef;
            P[j] = pnew;
        }

        wBuf[b][j] = pnew;
        if (j == 0) eBufB[b] = esum;
    }
}

__global__ void crf_combine_kernel(const float* __restrict__ trans,
                                   float* __restrict__ out) {
    __shared__ float sE[256];
    int t = threadIdx.x;
    sE[t] = __expf(trans[t]);
    __syncthreads();

    int b = blockIdx.x * 256 + t;

    float gv[16], wv[16];
    #pragma unroll
    for (int i = 0; i < 16; i++) gv[i] = gBuf[b][i];
    #pragma unroll
    for (int i = 0; i < 16; i++) wv[i] = wBuf[b][i];

    // fwd_arg = w^T M alpha
    double dot = 0.0;
    #pragma unroll
    for (int jj = 0; jj < 16; jj++) {
        float mg = 0.0f;
        #pragma unroll
        for (int i = 0; i < 16; i++) mg = fmaf(sE[jj * 16 + i], gv[i], mg);
        dot += (double)wv[jj] * (double)mg;
    }

    double fwd = (double)(eBufF[b] + eBufB[b]) * 0.6931471805599453 + log(dot);
    out[b] = (float)(fwd - (double)goldBuf[b]);
}

extern "C" void kernel_launch(void* const* d_in, const int* in_sizes, int n_in,
                              void* d_out, int out_size) {
    const float* feats = (const float*)d_in[0];
    const int*   tags  = (const int*)d_in[1];
    const float* trans = (const float*)d_in[2];
    float* out = (float*)d_out;

    crf_scan_kernel<<<128, 288>>>(feats, tags, trans);
    crf_combine_kernel<<<4, 256>>>(trans, out);
}